// round 12
// baseline (speedup 1.0000x reference)
#include <cuda_runtime.h>

#define SQ 512
#define DM 512
#define NH 8
#define DH 64
#define LSP 516   // padded logits stride

// ---------------- scratch (static device globals; no allocation) ----------------
__device__ __align__(16) float g_qu[NH*SQ*DH];   // (q proj)+u   [h][s][d]
__device__ __align__(16) float g_qv[NH*SQ*DH];   // (q proj)+v   [h][s][d]
__device__ __align__(16) float g_kh[NH*SQ*DH];   // k proj       [h][s][d]
__device__ __align__(16) float g_vh[NH*SQ*DH];   // v proj       [h][s][d]
__device__ __align__(16) float g_t [NH*SQ*SQ];   // t[h][q][D]
__device__ __align__(16) float g_ac[NH*SQ*SQ];   // A_C[h][q][k]
__device__ __align__(16) float g_at[NH*SQ*SQ];   // attn probs [h][q][k]
__device__ __align__(16) float g_op[4*NH*SQ*DH]; // K-split partials of out

__device__ __forceinline__ void ffma2(unsigned long long& d,
                                      unsigned long long a,
                                      unsigned long long b) {
    asm("fma.rn.f32x2 %0, %1, %2, %0;" : "+l"(d) : "l"(a), "l"(b));
}
__device__ __forceinline__ void cp16(unsigned saddr, const void* gptr) {
    asm volatile("cp.async.ca.shared.global [%0], [%1], 16;\n"
                 :: "r"(saddr), "l"(gptr));
}
__device__ __forceinline__ void cp_commit() {
    asm volatile("cp.async.commit_group;\n");
}
template<int N>
__device__ __forceinline__ void cp_wait() {
    asm volatile("cp.async.wait_group %0;\n" :: "n"(N));
}

// ---------------- K0: no-op filler so attn_kernel is launch #4 (ncu window) ----
__global__ void warmup_kernel() {}

// ---------------- K1: q/k/v projections (fused via blockIdx.z) ----------------
__global__ void __launch_bounds__(256) proj_kernel(
    const float* __restrict__ Xq, const float* __restrict__ Xk, const float* __restrict__ Xv,
    const float* __restrict__ Wq, const float* __restrict__ bq,
    const float* __restrict__ Wk, const float* __restrict__ bk,
    const float* __restrict__ Wv, const float* __restrict__ bv,
    const float* __restrict__ u,  const float* __restrict__ v)
{
    const int mode = blockIdx.z;
    const float* X    = (mode == 0) ? Xq : (mode == 1) ? Xk : Xv;
    const float* W    = (mode == 0) ? Wq : (mode == 1) ? Wk : Wv;
    const float* bias = (mode == 0) ? bq : (mode == 1) ? bk : bv;

    __shared__ __align__(16) float As[16][64];
    __shared__ __align__(16) float Bs[16][64];

    const int tid = threadIdx.x;
    const int m0 = blockIdx.y * 64, n0 = blockIdx.x * 64;
    const int ty = tid >> 4, tx = tid & 15;
    const int aRow = tid >> 2, aK = (tid & 3) * 4;
    const int bK = tid >> 4, bN = (tid & 15) * 4;

    float c[4][4] = {};

    for (int k0 = 0; k0 < DM; k0 += 16) {
        float4 av = *(const float4*)&X[(size_t)(m0 + aRow) * DM + k0 + aK];
        As[aK + 0][aRow] = av.x; As[aK + 1][aRow] = av.y;
        As[aK + 2][aRow] = av.z; As[aK + 3][aRow] = av.w;
        *(float4*)&Bs[bK][bN] = *(const float4*)&W[(size_t)(k0 + bK) * DM + n0 + bN];
        __syncthreads();
        #pragma unroll
        for (int kk = 0; kk < 16; kk++) {
            float4 a4 = *(float4*)&As[kk][ty * 4];
            float4 b4 = *(float4*)&Bs[kk][tx * 4];
            float aa[4] = {a4.x, a4.y, a4.z, a4.w};
            float bb[4] = {b4.x, b4.y, b4.z, b4.w};
            #pragma unroll
            for (int i = 0; i < 4; i++)
                #pragma unroll
                for (int j = 0; j < 4; j++)
                    c[i][j] += aa[i] * bb[j];
        }
        __syncthreads();
    }

    #pragma unroll
    for (int i = 0; i < 4; i++) {
        int s = m0 + ty * 4 + i;
        #pragma unroll
        for (int j = 0; j < 4; j++) {
            int n = n0 + tx * 4 + j;
            float val = c[i][j] + bias[n];
            int h = n >> 6, d = n & 63;
            size_t o = (size_t)h * SQ * DH + (size_t)s * DH + d;
            if (mode == 0) {
                g_qu[o] = val + u[n];
                g_qv[o] = val + v[n];
            } else if (mode == 1) {
                g_kh[o] = val;
            } else {
                g_vh[o] = val;
            }
        }
    }
}

// ---------------- K2: fused NT GEMMs (K=64): A_C and t ----------------
__global__ void __launch_bounds__(256) nt64_kernel(const float* __restrict__ Wr)
{
    const int z = blockIdx.z;
    const int h = z & 7;
    const int which = z >> 3;
    const int n0 = blockIdx.x * 64, m0 = blockIdx.y * 64;

    __shared__ __align__(16) float Am[64][68];
    __shared__ __align__(16) float Bm[64][68];

    const int tid = threadIdx.x;
    const float* A = (which ? g_qv : g_qu) + (size_t)h * SQ * DH;
    const int rr = tid >> 4, d4 = (tid & 15) * 4;

    #pragma unroll
    for (int r = 0; r < 4; r++) {
        int m = rr + r * 16;
        float4 av = *(const float4*)&A[(size_t)(m0 + m) * DH + d4];
        Am[d4 + 0][m] = av.x; Am[d4 + 1][m] = av.y;
        Am[d4 + 2][m] = av.z; Am[d4 + 3][m] = av.w;
        float4 bv;
        if (which == 0)
            bv = *(const float4*)&g_kh[(size_t)h * SQ * DH + (size_t)(n0 + m) * DH + d4];
        else
            bv = *(const float4*)&Wr[(size_t)(n0 + m) * DM + h * DH + d4];
        Bm[d4 + 0][m] = bv.x; Bm[d4 + 1][m] = bv.y;
        Bm[d4 + 2][m] = bv.z; Bm[d4 + 3][m] = bv.w;
    }
    __syncthreads();

    const int ty = tid >> 4, tx = tid & 15;
    float c[4][4] = {};
    #pragma unroll 8
    for (int dd = 0; dd < 64; dd++) {
        float4 a4 = *(float4*)&Am[dd][ty * 4];
        float4 b4 = *(float4*)&Bm[dd][tx * 4];
        float aa[4] = {a4.x, a4.y, a4.z, a4.w};
        float bb[4] = {b4.x, b4.y, b4.z, b4.w};
        #pragma unroll
        for (int i = 0; i < 4; i++)
            #pragma unroll
            for (int j = 0; j < 4; j++)
                c[i][j] += aa[i] * bb[j];
    }

    float* Out = which ? g_t : g_ac;
    #pragma unroll
    for (int i = 0; i < 4; i++)
        #pragma unroll
        for (int j = 0; j < 4; j++)
            Out[(size_t)h * SQ * SQ + (size_t)(m0 + ty * 4 + i) * SQ + (n0 + tx * 4 + j)] = c[i][j];
}

// ---------------- K3: B_D + logits + fused softmax (cp.async staged) --------
// One CTA (512 thr, 16 warps) per query q, occ 1. Stage = 32 key rows (64 KB)
// double-buffered via cp.async. Warp w computes rows 2w, 2w+1; lanes split D
// (16B slices) -> conflict-free LDS.128. Multi-value butterfly (9 shfl) per
// row for the 8 head-sums. Softmax fused (warps 0-7 = heads 0-7).
// Dynamic smem: ring 128KB | t 16KB | logits 16.5KB = 163968 B -> 1 CTA/SM.
__global__ void __launch_bounds__(512, 1) attn_kernel(
    const float* __restrict__ rel, const int* __restrict__ rlen,
    const int* __restrict__ lexp)
{
    extern __shared__ __align__(16) char smem_raw[];
    float* ring = (float*)smem_raw;               // 2 * 32 * 512 floats = 128 KB
    float* tf   = ring + 2 * 32 * 512;            // 8*512 floats (t[h][D])
    float* ls   = tf + NH * SQ;                   // 8*516 floats (logits)
    ulonglong2* t2s = (ulonglong2*)tf;

    const int q = blockIdx.x;
    const int tid = threadIdx.x;
    const int w = tid >> 5, lane = tid & 31;

    // init t + logits(A_C) smem (coalesced)
    for (int i = tid; i < NH * SQ; i += 512) {
        int h = i >> 9, kD = i & 511;
        tf[i] = g_t[(size_t)h * SQ * SQ + (size_t)q * SQ + kD];
        ls[h * LSP + kD] = g_ac[(size_t)h * SQ * SQ + (size_t)q * SQ + kD];
    }

    int len = rlen[0] + (lexp ? lexp[0] : 64);
    if (len > SQ) len = SQ;
    if (len < 1) len = 1;
    const int nst = (len + 31) >> 5;   // stages of 32 rows

    unsigned rbase = (unsigned)__cvta_generic_to_shared(ring);
    const char* grel = (const char*)(rel + (size_t)q * SQ * DM);

    // prefetch stage 0 (64 KB, 8 cp16 per thread, coalesced)
    #pragma unroll
    for (int i = 0; i < 8; i++)
        cp16(rbase + (tid + i * 512) * 16, grel + (tid + i * 512) * 16);
    cp_commit();

    __syncthreads();   // t/ls visible before compute

    const bool hi4 = (lane & 16) != 0;
    const bool hi2 = (lane & 8)  != 0;
    const bool hi1 = (lane & 4)  != 0;
    const int  myh = (lane >> 2) & 7;

    for (int s = 0; s < nst; s++) {
        if (s + 1 < nst) {
            const char* gs = grel + (size_t)(s + 1) * 32 * DM * 4;
            unsigned sb = rbase + ((s + 1) & 1) * 65536;
            #pragma unroll
            for (int i = 0; i < 8; i++)
                cp16(sb + (tid + i * 512) * 16, gs + (tid + i * 512) * 16);
        }
        cp_commit();        // (possibly empty group on last iter)
        cp_wait<1>();       // stage s complete
        __syncthreads();

        const float* rb = ring + (s & 1) * 16384;
        unsigned long long acc[2][8];
        #pragma unroll
        for (int r = 0; r < 2; r++)
            #pragma unroll
            for (int h = 0; h < 8; h++) acc[r][h] = 0ULL;

        #pragma unroll
        for (int c = 0; c < 4; c++) {
            ulonglong2 tc[8];
            #pragma unroll
            for (int h = 0; h < 8; h++) tc[h] = t2s[h * 128 + c * 32 + lane];
            #pragma unroll
            for (int r = 0; r < 2; r++) {
                ulonglong2 rv = *(const ulonglong2*)&rb[(w * 2 + r) * 512 + (c * 32 + lane) * 4];
                #pragma unroll
                for (int h = 0; h < 8; h++) {
                    ffma2(acc[r][h], rv.x, tc[h].x);
                    ffma2(acc[r][h], rv.y, tc[h].y);
                }
            }
        }

        #pragma unroll
        for (int r = 0; r < 2; r++) {
            float v[8];
            #pragma unroll
            for (int h = 0; h < 8; h++) {
                float2 p = *(float2*)&acc[r][h];
                v[h] = p.x + p.y;
            }
            float u4[4];
            #pragma unroll
            for (int i = 0; i < 4; i++) {
                float send = hi4 ? v[i] : v[i + 4];
                float keep = hi4 ? v[i + 4] : v[i];
                u4[i] = keep + __shfl_xor_sync(0xffffffffu, send, 16);
            }
            float u2[2];
            #pragma unroll
            for (int i = 0; i < 2; i++) {
                float send = hi2 ? u4[i] : u4[i + 2];
                float keep = hi2 ? u4[i + 2] : u4[i];
                u2[i] = keep + __shfl_xor_sync(0xffffffffu, send, 8);
            }
            float send = hi1 ? u2[0] : u2[1];
            float keep = hi1 ? u2[1] : u2[0];
            float sv = keep + __shfl_xor_sync(0xffffffffu, send, 4);
            sv += __shfl_xor_sync(0xffffffffu, sv, 2);
            sv += __shfl_xor_sync(0xffffffffu, sv, 1);
            if ((lane & 3) == 0)
                ls[myh * LSP + (s * 32 + w * 2 + r)] += sv;
        }
        __syncthreads();   // all warps done with buf before it is re-filled
    }

    // fused softmax: warps 0-7 = heads 0-7 (16 keys per lane)
    if (w < NH) {
        float vb[16];
        float m = -3.4e38f;
        #pragma unroll
        for (int r = 0; r < 16; r++) {
            int k = r * 32 + lane;
            vb[r] = (k < len) ? ls[w * LSP + k] : -3.0e38f;
            m = fmaxf(m, vb[r]);
        }
        #pragma unroll
        for (int o = 16; o; o >>= 1) m = fmaxf(m, __shfl_xor_sync(0xffffffffu, m, o));
        float sum = 0.f;
        #pragma unroll
        for (int r = 0; r < 16; r++) { vb[r] = __expf(vb[r] - m); sum += vb[r]; }
        #pragma unroll
        for (int o = 16; o; o >>= 1) sum += __shfl_xor_sync(0xffffffffu, sum, o);
        float inv = 1.0f / sum;
        #pragma unroll
        for (int r = 0; r < 16; r++)
            g_at[(size_t)w * SQ * SQ + (size_t)q * SQ + r * 32 + lane] = vb[r] * inv;
    }
}

// ---------------- K4: out partials, K-split x4 ----------------
__global__ void __launch_bounds__(256) av_kernel()
{
    const int h = blockIdx.y;
    const int q0 = blockIdx.x * 32;
    const int kz = blockIdx.z;

    __shared__ __align__(16) float As[16][36];
    __shared__ __align__(16) float Bs[16][64];

    const int tid = threadIdx.x;
    const int aq = tid >> 3, ak = (tid & 7) * 2;
    const int bk = tid >> 4, bd = (tid & 15) * 4;
    const int ty = tid >> 5;
    const int tx = tid & 31;

    float c[4][2] = {};

    for (int kc = kz * 128; kc < kz * 128 + 128; kc += 16) {
        float2 a2 = *(const float2*)&g_at[(size_t)h * SQ * SQ + (size_t)(q0 + aq) * SQ + kc + ak];
        As[ak][aq] = a2.x; As[ak + 1][aq] = a2.y;
        *(float4*)&Bs[bk][bd] =
            *(const float4*)&g_vh[(size_t)h * SQ * DH + (size_t)(kc + bk) * DH + bd];
        __syncthreads();
        #pragma unroll
        for (int kk = 0; kk < 16; kk++) {
            float4 a4 = *(float4*)&As[kk][ty * 4];
            float b0 = Bs[kk][tx], b1 = Bs[kk][tx + 32];
            float aa[4] = {a4.x, a4.y, a4.z, a4.w};
            #pragma unroll
            for (int i = 0; i < 4; i++) {
                c[i][0] += aa[i] * b0;
                c[i][1] += aa[i] * b1;
            }
        }
        __syncthreads();
    }

    #pragma unroll
    for (int i = 0; i < 4; i++) {
        size_t o = (size_t)(kz * NH + h) * SQ * DH + (size_t)(q0 + ty * 4 + i) * DH;
        g_op[o + tx]      = c[i][0];
        g_op[o + tx + 32] = c[i][1];
    }
}

// ---------------- K5: residual + K-split reduce + LayerNorm ----------------
__global__ void __launch_bounds__(512) ln_kernel(const float* __restrict__ query,
                                                 float* __restrict__ out)
{
    __shared__ float red[32];
    const int s = blockIdx.x, j = threadIdx.x;
    const int h = j >> 6, d = j & 63;
    float x = query[(size_t)s * DM + j];
    #pragma unroll
    for (int kz = 0; kz < 4; kz++)
        x += g_op[(size_t)(kz * NH + h) * SQ * DH + (size_t)s * DH + d];
    float v1 = x, v2 = x * x;
    #pragma unroll
    for (int o = 16; o; o >>= 1) {
        v1 += __shfl_xor_sync(0xffffffffu, v1, o);
        v2 += __shfl_xor_sync(0xffffffffu, v2, o);
    }
    const int w = j >> 5;
    if ((j & 31) == 0) { red[w] = v1; red[w + 16] = v2; }
    __syncthreads();
    if (j < 32) {
        float a = (j < 16) ? red[j] : 0.f;
        float b = (j < 16) ? red[j + 16] : 0.f;
        #pragma unroll
        for (int o = 8; o; o >>= 1) {
            a += __shfl_xor_sync(0xffffffffu, a, o);
            b += __shfl_xor_sync(0xffffffffu, b, o);
        }
        if (j == 0) { red[0] = a; red[1] = b; }
    }
    __syncthreads();
    float mean = red[0] * (1.f / 512.f);
    float var  = red[1] * (1.f / 512.f) - mean * mean;
    out[(size_t)s * DM + j] = (x - mean) * rsqrtf(var + 1e-5f);
}

// ---------------- launch ----------------
extern "C" void kernel_launch(void* const* d_in, const int* in_sizes, int n_in,
                              void* d_out, int out_size)
{
    const float* query = (const float*)d_in[0];
    const float* key   = (const float*)d_in[1];
    const float* value = (const float*)d_in[2];
    const float* rel   = (const float*)d_in[3];
    const int*   rlen  = (const int*)d_in[4];

    int base = 5;
    const int* lexp = nullptr;
    if (n_in >= 16 && in_sizes[5] == 1) { lexp = (const int*)d_in[5]; base = 6; }

    const float* Wq = (const float*)d_in[base + 0];
    const float* bq = (const float*)d_in[base + 1];
    const float* Wk = (const float*)d_in[base + 2];
    const float* bk = (const float*)d_in[base + 3];
    const float* Wv = (const float*)d_in[base + 4];
    const float* bv = (const float*)d_in[base + 5];
    const float* Wr = (const float*)d_in[base + 6];
    // br (base+7) is constant per (h,q) row -> drops out of softmax (and is zero)
    const float* u  = (const float*)d_in[base + 8];
    const float* v  = (const float*)d_in[base + 9];
    (void)out_size;

    const int ATTN_SMEM = 2 * 32 * 512 * 4 + NH * SQ * 4 + NH * LSP * 4;  // 163968
    cudaFuncSetAttribute(attn_kernel, cudaFuncAttributeMaxDynamicSharedMemorySize, ATTN_SMEM);

    warmup_kernel<<<1, 32>>>();   // filler: makes attn_kernel launch #4 for the ncu window
    proj_kernel<<<dim3(8, 8, 3), 256>>>(query, key, value, Wq, bq, Wk, bk, Wv, bv, u, v);
    nt64_kernel<<<dim3(8, 8, 16), 256>>>(Wr);
    attn_kernel<<<SQ, 512, ATTN_SMEM>>>(rel, rlen, lexp);
    av_kernel<<<dim3(16, 8, 4), 256>>>();
    ln_kernel<<<SQ, 512>>>(query, (float*)d_out);
}

// round 13
// speedup vs baseline: 1.7499x; 1.7499x over previous
#include <cuda_runtime.h>

#define SQ 512
#define DM 512
#define NH 8
#define DH 64
#define LSP 516   // padded logits stride

// ---------------- scratch (static device globals; no allocation) ----------------
__device__ __align__(16) float g_qu[NH*SQ*DH];   // (q proj)+u   [h][s][d]
__device__ __align__(16) float g_qv[NH*SQ*DH];   // (q proj)+v   [h][s][d]
__device__ __align__(16) float g_kh[NH*SQ*DH];   // k proj       [h][s][d]
__device__ __align__(16) float g_vh[NH*SQ*DH];   // v proj       [h][s][d]
__device__ __align__(16) float g_t [NH*SQ*SQ];   // t[h][q][D]
__device__ __align__(16) float g_ac[NH*SQ*SQ];   // A_C[h][q][k]
__device__ __align__(16) float g_at[NH*SQ*SQ];   // attn probs [h][q][k]
__device__ __align__(16) float g_op[4*NH*SQ*DH]; // K-split partials of out

__device__ __forceinline__ void ffma2(unsigned long long& d,
                                      unsigned long long a,
                                      unsigned long long b) {
    asm("fma.rn.f32x2 %0, %1, %2, %0;" : "+l"(d) : "l"(a), "l"(b));
}
__device__ __forceinline__ void cp16(unsigned saddr, const void* gptr) {
    asm volatile("cp.async.ca.shared.global [%0], [%1], 16;\n"
                 :: "r"(saddr), "l"(gptr));
}
__device__ __forceinline__ void cp_commit() {
    asm volatile("cp.async.commit_group;\n");
}
template<int N>
__device__ __forceinline__ void cp_wait() {
    asm volatile("cp.async.wait_group %0;\n" :: "n"(N));
}

// ---------------- K0: no-op filler so attn_kernel is launch #4 (ncu window) ----
__global__ void warmup_kernel() {}

// ---------------- K1: q/k/v projections (fused via blockIdx.z) ----------------
__global__ void __launch_bounds__(256) proj_kernel(
    const float* __restrict__ Xq, const float* __restrict__ Xk, const float* __restrict__ Xv,
    const float* __restrict__ Wq, const float* __restrict__ bq,
    const float* __restrict__ Wk, const float* __restrict__ bk,
    const float* __restrict__ Wv, const float* __restrict__ bv,
    const float* __restrict__ u,  const float* __restrict__ v)
{
    const int mode = blockIdx.z;
    const float* X    = (mode == 0) ? Xq : (mode == 1) ? Xk : Xv;
    const float* W    = (mode == 0) ? Wq : (mode == 1) ? Wk : Wv;
    const float* bias = (mode == 0) ? bq : (mode == 1) ? bk : bv;

    __shared__ __align__(16) float As[16][64];
    __shared__ __align__(16) float Bs[16][64];

    const int tid = threadIdx.x;
    const int m0 = blockIdx.y * 64, n0 = blockIdx.x * 64;
    const int ty = tid >> 4, tx = tid & 15;
    const int aRow = tid >> 2, aK = (tid & 3) * 4;
    const int bK = tid >> 4, bN = (tid & 15) * 4;

    float c[4][4] = {};

    for (int k0 = 0; k0 < DM; k0 += 16) {
        float4 av = *(const float4*)&X[(size_t)(m0 + aRow) * DM + k0 + aK];
        As[aK + 0][aRow] = av.x; As[aK + 1][aRow] = av.y;
        As[aK + 2][aRow] = av.z; As[aK + 3][aRow] = av.w;
        *(float4*)&Bs[bK][bN] = *(const float4*)&W[(size_t)(k0 + bK) * DM + n0 + bN];
        __syncthreads();
        #pragma unroll
        for (int kk = 0; kk < 16; kk++) {
            float4 a4 = *(float4*)&As[kk][ty * 4];
            float4 b4 = *(float4*)&Bs[kk][tx * 4];
            float aa[4] = {a4.x, a4.y, a4.z, a4.w};
            float bb[4] = {b4.x, b4.y, b4.z, b4.w};
            #pragma unroll
            for (int i = 0; i < 4; i++)
                #pragma unroll
                for (int j = 0; j < 4; j++)
                    c[i][j] += aa[i] * bb[j];
        }
        __syncthreads();
    }

    #pragma unroll
    for (int i = 0; i < 4; i++) {
        int s = m0 + ty * 4 + i;
        #pragma unroll
        for (int j = 0; j < 4; j++) {
            int n = n0 + tx * 4 + j;
            float val = c[i][j] + bias[n];
            int h = n >> 6, d = n & 63;
            size_t o = (size_t)h * SQ * DH + (size_t)s * DH + d;
            if (mode == 0) {
                g_qu[o] = val + u[n];
                g_qv[o] = val + v[n];
            } else if (mode == 1) {
                g_kh[o] = val;
            } else {
                g_vh[o] = val;
            }
        }
    }
}

// ---------------- K2: fused NT GEMMs (K=64): A_C and t ----------------
__global__ void __launch_bounds__(256) nt64_kernel(const float* __restrict__ Wr)
{
    const int z = blockIdx.z;
    const int h = z & 7;
    const int which = z >> 3;
    const int n0 = blockIdx.x * 64, m0 = blockIdx.y * 64;

    __shared__ __align__(16) float Am[64][68];
    __shared__ __align__(16) float Bm[64][68];

    const int tid = threadIdx.x;
    const float* A = (which ? g_qv : g_qu) + (size_t)h * SQ * DH;
    const int rr = tid >> 4, d4 = (tid & 15) * 4;

    #pragma unroll
    for (int r = 0; r < 4; r++) {
        int m = rr + r * 16;
        float4 av = *(const float4*)&A[(size_t)(m0 + m) * DH + d4];
        Am[d4 + 0][m] = av.x; Am[d4 + 1][m] = av.y;
        Am[d4 + 2][m] = av.z; Am[d4 + 3][m] = av.w;
        float4 bv;
        if (which == 0)
            bv = *(const float4*)&g_kh[(size_t)h * SQ * DH + (size_t)(n0 + m) * DH + d4];
        else
            bv = *(const float4*)&Wr[(size_t)(n0 + m) * DM + h * DH + d4];
        Bm[d4 + 0][m] = bv.x; Bm[d4 + 1][m] = bv.y;
        Bm[d4 + 2][m] = bv.z; Bm[d4 + 3][m] = bv.w;
    }
    __syncthreads();

    const int ty = tid >> 4, tx = tid & 15;
    float c[4][4] = {};
    #pragma unroll 8
    for (int dd = 0; dd < 64; dd++) {
        float4 a4 = *(float4*)&Am[dd][ty * 4];
        float4 b4 = *(float4*)&Bm[dd][tx * 4];
        float aa[4] = {a4.x, a4.y, a4.z, a4.w};
        float bb[4] = {b4.x, b4.y, b4.z, b4.w};
        #pragma unroll
        for (int i = 0; i < 4; i++)
            #pragma unroll
            for (int j = 0; j < 4; j++)
                c[i][j] += aa[i] * bb[j];
    }

    float* Out = which ? g_t : g_ac;
    #pragma unroll
    for (int i = 0; i < 4; i++)
        #pragma unroll
        for (int j = 0; j < 4; j++)
            Out[(size_t)h * SQ * SQ + (size_t)(m0 + ty * 4 + i) * SQ + (n0 + tx * 4 + j)] = c[i][j];
}

// ---------------- K3: B_D + logits + fused softmax (cp.async staged) --------
// One CTA (256 thr, 8 warps) per query q, 2 CTAs/SM. Stage = 16 key rows
// (32 KB) double-buffered via cp.async. Head-split: warp w owns heads
// hb=(w>>2)*4..+3 and in-stage rows (w&3)*4..+3. t chunks for the warp's 4
// heads are REGISTER-PERSISTENT across all stages (loaded once) -> per-stage
// smem reads are only the 16 rel LDS.128/warp. Rows processed in 2 passes of
// 2 (acc[2][4]) to stay under the 128-reg cap. 4-value butterfly reduction
// (head=(lane>>3)&3, writers (lane&7)==0). Softmax fused (warp w = head w).
// Dynamic smem: ring 64KB | t 16KB | logits 16.5KB = 98432 B.
__global__ void __launch_bounds__(256, 2) attn_kernel(
    const float* __restrict__ rel, const int* __restrict__ rlen,
    const int* __restrict__ lexp)
{
    extern __shared__ __align__(16) char smem_raw[];
    float* ring = (float*)smem_raw;               // 2 * 16 * 512 floats = 64 KB
    float* tf   = ring + 2 * 16 * 512;            // 8*512 floats (t[h][D])
    float* ls   = tf + NH * SQ;                   // 8*516 floats (logits)
    ulonglong2* t2s = (ulonglong2*)tf;

    const int q = blockIdx.x;
    const int tid = threadIdx.x;
    const int w = tid >> 5, lane = tid & 31;

    // init t + logits(A_C) smem (coalesced)
    for (int i = tid; i < NH * SQ; i += 256) {
        int h = i >> 9, kD = i & 511;
        tf[i] = g_t[(size_t)h * SQ * SQ + (size_t)q * SQ + kD];
        ls[h * LSP + kD] = g_ac[(size_t)h * SQ * SQ + (size_t)q * SQ + kD];
    }

    int len = rlen[0] + (lexp ? lexp[0] : 64);
    if (len > SQ) len = SQ;
    if (len < 1) len = 1;
    const int nst = (len + 15) >> 4;   // stages of 16 rows

    unsigned rsb = (unsigned)__cvta_generic_to_shared(ring);
    const char* grel = (const char*)(rel + (size_t)q * SQ * DM);

    // prefetch stage 0 (32 KB, 8 cp16/thread, coalesced)
    #pragma unroll
    for (int i = 0; i < 8; i++)
        cp16(rsb + (tid + i * 256) * 16, grel + (tid + i * 256) * 16);
    cp_commit();

    __syncthreads();   // tf/ls visible before tc loads

    const int hb = (w >> 2) * 4;       // this warp's head base
    const int rbase = (w & 3) * 4;     // this warp's in-stage row base

    // register-persistent t chunks: tc[c][h2], loaded ONCE
    ulonglong2 tc[4][4];
    #pragma unroll
    for (int c = 0; c < 4; c++)
        #pragma unroll
        for (int h2 = 0; h2 < 4; h2++)
            tc[c][h2] = t2s[(hb + h2) * 128 + c * 32 + lane];

    const bool hi4 = (lane & 16) != 0;
    const bool hi2 = (lane & 8)  != 0;
    const int  myh = (lane >> 3) & 3;

    for (int s = 0; s < nst; s++) {
        if (s + 1 < nst) {
            const char* gs = grel + (size_t)(s + 1) * 16 * DM * 4;
            unsigned sb = rsb + ((s + 1) & 1) * 32768;
            #pragma unroll
            for (int i = 0; i < 8; i++)
                cp16(sb + (tid + i * 256) * 16, gs + (tid + i * 256) * 16);
        }
        cp_commit();        // (possibly empty group on last iter)
        cp_wait<1>();       // stage s complete
        __syncthreads();

        const float* rb = ring + (s & 1) * 8192;

        #pragma unroll
        for (int r2 = 0; r2 < 2; r2++) {
            unsigned long long acc[2][4];
            #pragma unroll
            for (int rr = 0; rr < 2; rr++)
                #pragma unroll
                for (int h2 = 0; h2 < 4; h2++) acc[rr][h2] = 0ULL;

            #pragma unroll
            for (int c = 0; c < 4; c++) {
                #pragma unroll
                for (int rr = 0; rr < 2; rr++) {
                    ulonglong2 rv = *(const ulonglong2*)
                        &rb[(rbase + r2 * 2 + rr) * 512 + (c * 32 + lane) * 4];
                    #pragma unroll
                    for (int h2 = 0; h2 < 4; h2++) {
                        ffma2(acc[rr][h2], rv.x, tc[c][h2].x);
                        ffma2(acc[rr][h2], rv.y, tc[c][h2].y);
                    }
                }
            }

            #pragma unroll
            for (int rr = 0; rr < 2; rr++) {
                float v[4];
                #pragma unroll
                for (int h2 = 0; h2 < 4; h2++) {
                    float2 p = *(float2*)&acc[rr][h2];
                    v[h2] = p.x + p.y;
                }
                // level 16: head bit1 <- lane bit4
                float u2[2];
                #pragma unroll
                for (int i = 0; i < 2; i++) {
                    float send = hi4 ? v[i] : v[i + 2];
                    float keep = hi4 ? v[i + 2] : v[i];
                    u2[i] = keep + __shfl_xor_sync(0xffffffffu, send, 16);
                }
                // level 8: head bit0 <- lane bit3
                float send = hi2 ? u2[0] : u2[1];
                float keep = hi2 ? u2[1] : u2[0];
                float sv = keep + __shfl_xor_sync(0xffffffffu, send, 8);
                sv += __shfl_xor_sync(0xffffffffu, sv, 4);
                sv += __shfl_xor_sync(0xffffffffu, sv, 2);
                sv += __shfl_xor_sync(0xffffffffu, sv, 1);
                if ((lane & 7) == 0)
                    ls[(hb + myh) * LSP + (s * 16 + rbase + r2 * 2 + rr)] += sv;
            }
        }
        __syncthreads();   // all warps done with buf before it is re-filled
    }

    // fused softmax: warp w = head w (16 keys per lane)
    {
        float vb[16];
        float m = -3.4e38f;
        #pragma unroll
        for (int r = 0; r < 16; r++) {
            int k = r * 32 + lane;
            vb[r] = (k < len) ? ls[w * LSP + k] : -3.0e38f;
            m = fmaxf(m, vb[r]);
        }
        #pragma unroll
        for (int o = 16; o; o >>= 1) m = fmaxf(m, __shfl_xor_sync(0xffffffffu, m, o));
        float sum = 0.f;
        #pragma unroll
        for (int r = 0; r < 16; r++) { vb[r] = __expf(vb[r] - m); sum += vb[r]; }
        #pragma unroll
        for (int o = 16; o; o >>= 1) sum += __shfl_xor_sync(0xffffffffu, sum, o);
        float inv = 1.0f / sum;
        #pragma unroll
        for (int r = 0; r < 16; r++)
            g_at[(size_t)w * SQ * SQ + (size_t)q * SQ + r * 32 + lane] = vb[r] * inv;
    }
}

// ---------------- K4: out partials, K-split x4 ----------------
__global__ void __launch_bounds__(256) av_kernel()
{
    const int h = blockIdx.y;
    const int q0 = blockIdx.x * 32;
    const int kz = blockIdx.z;

    __shared__ __align__(16) float As[16][36];
    __shared__ __align__(16) float Bs[16][64];

    const int tid = threadIdx.x;
    const int aq = tid >> 3, ak = (tid & 7) * 2;
    const int bk = tid >> 4, bd = (tid & 15) * 4;
    const int ty = tid >> 5;
    const int tx = tid & 31;

    float c[4][2] = {};

    for (int kc = kz * 128; kc < kz * 128 + 128; kc += 16) {
        float2 a2 = *(const float2*)&g_at[(size_t)h * SQ * SQ + (size_t)(q0 + aq) * SQ + kc + ak];
        As[ak][aq] = a2.x; As[ak + 1][aq] = a2.y;
        *(float4*)&Bs[bk][bd] =
            *(const float4*)&g_vh[(size_t)h * SQ * DH + (size_t)(kc + bk) * DH + bd];
        __syncthreads();
        #pragma unroll
        for (int kk = 0; kk < 16; kk++) {
            float4 a4 = *(float4*)&As[kk][ty * 4];
            float b0 = Bs[kk][tx], b1 = Bs[kk][tx + 32];
            float aa[4] = {a4.x, a4.y, a4.z, a4.w};
            #pragma unroll
            for (int i = 0; i < 4; i++) {
                c[i][0] += aa[i] * b0;
                c[i][1] += aa[i] * b1;
            }
        }
        __syncthreads();
    }

    #pragma unroll
    for (int i = 0; i < 4; i++) {
        size_t o = (size_t)(kz * NH + h) * SQ * DH + (size_t)(q0 + ty * 4 + i) * DH;
        g_op[o + tx]      = c[i][0];
        g_op[o + tx + 32] = c[i][1];
    }
}

// ---------------- K5: residual + K-split reduce + LayerNorm ----------------
__global__ void __launch_bounds__(512) ln_kernel(const float* __restrict__ query,
                                                 float* __restrict__ out)
{
    __shared__ float red[32];
    const int s = blockIdx.x, j = threadIdx.x;
    const int h = j >> 6, d = j & 63;
    float x = query[(size_t)s * DM + j];
    #pragma unroll
    for (int kz = 0; kz < 4; kz++)
        x += g_op[(size_t)(kz * NH + h) * SQ * DH + (size_t)s * DH + d];
    float v1 = x, v2 = x * x;
    #pragma unroll
    for (int o = 16; o; o >>= 1) {
        v1 += __shfl_xor_sync(0xffffffffu, v1, o);
        v2 += __shfl_xor_sync(0xffffffffu, v2, o);
    }
    const int w = j >> 5;
    if ((j & 31) == 0) { red[w] = v1; red[w + 16] = v2; }
    __syncthreads();
    if (j < 32) {
        float a = (j < 16) ? red[j] : 0.f;
        float b = (j < 16) ? red[j + 16] : 0.f;
        #pragma unroll
        for (int o = 8; o; o >>= 1) {
            a += __shfl_xor_sync(0xffffffffu, a, o);
            b += __shfl_xor_sync(0xffffffffu, b, o);
        }
        if (j == 0) { red[0] = a; red[1] = b; }
    }
    __syncthreads();
    float mean = red[0] * (1.f / 512.f);
    float var  = red[1] * (1.f / 512.f) - mean * mean;
    out[(size_t)s * DM + j] = (x - mean) * rsqrtf(var + 1e-5f);
}

// ---------------- launch ----------------
extern "C" void kernel_launch(void* const* d_in, const int* in_sizes, int n_in,
                              void* d_out, int out_size)
{
    const float* query = (const float*)d_in[0];
    const float* key   = (const float*)d_in[1];
    const float* value = (const float*)d_in[2];
    const float* rel   = (const float*)d_in[3];
    const int*   rlen  = (const int*)d_in[4];

    int base = 5;
    const int* lexp = nullptr;
    if (n_in >= 16 && in_sizes[5] == 1) { lexp = (const int*)d_in[5]; base = 6; }

    const float* Wq = (const float*)d_in[base + 0];
    const float* bq = (const float*)d_in[base + 1];
    const float* Wk = (const float*)d_in[base + 2];
    const float* bk = (const float*)d_in[base + 3];
    const float* Wv = (const float*)d_in[base + 4];
    const float* bv = (const float*)d_in[base + 5];
    const float* Wr = (const float*)d_in[base + 6];
    // br (base+7) is constant per (h,q) row -> drops out of softmax (and is zero)
    const float* u  = (const float*)d_in[base + 8];
    const float* v  = (const float*)d_in[base + 9];
    (void)out_size;

    const int ATTN_SMEM = 2 * 16 * 512 * 4 + NH * SQ * 4 + NH * LSP * 4;  // 98432
    cudaFuncSetAttribute(attn_kernel, cudaFuncAttributeMaxDynamicSharedMemorySize, ATTN_SMEM);

    warmup_kernel<<<1, 32>>>();   // filler: keeps attn_kernel at launch #4 (ncu window)
    proj_kernel<<<dim3(8, 8, 3), 256>>>(query, key, value, Wq, bq, Wk, bk, Wv, bv, u, v);
    nt64_kernel<<<dim3(8, 8, 16), 256>>>(Wr);
    attn_kernel<<<SQ, 256, ATTN_SMEM>>>(rel, rlen, lexp);
    av_kernel<<<dim3(16, 8, 4), 256>>>();
    ln_kernel<<<SQ, 512>>>(query, (float*)d_out);
}